// round 7
// baseline (speedup 1.0000x reference)
#include <cuda_runtime.h>
#include <cuda_fp16.h>
#include <mma.h>
#include <cstdint>

using namespace nvcuda;

#define BATCH   2
#define SEQ     8192
#define DMODEL  1024
#define NHEADS  16
#define HD      64
#define NBLK    64
#define BS      128

// ---------------------------------------------------------------------------
// Device scratch
// ---------------------------------------------------------------------------
__device__ __half g_xh[(size_t)BATCH * SEQ * DMODEL];        // fp16 GEMM input
__device__ __half g_wq[(size_t)DMODEL * DMODEL];
__device__ __half g_wk[(size_t)DMODEL * DMODEL];
__device__ __half g_wv[(size_t)DMODEL * DMODEL];
__device__ __half g_wo[(size_t)DMODEL * DMODEL];
__device__ __half g_qh[(size_t)BATCH * NHEADS * SEQ * HD];   // fp16 q/k/v
__device__ __half g_kh[(size_t)BATCH * NHEADS * SEQ * HD];
__device__ __half g_vh[(size_t)BATCH * NHEADS * SEQ * HD];
__device__ __half g_attnh[(size_t)BATCH * SEQ * DMODEL];     // fp16 attn out

// ---------------------------------------------------------------------------
// fp32 -> fp16 conversion
// ---------------------------------------------------------------------------
__global__ void f2h_kernel(const float* __restrict__ src, __half* __restrict__ dst, int n4)
{
    int i = blockIdx.x * blockDim.x + threadIdx.x;
    for (; i < n4; i += gridDim.x * blockDim.x) {
        float4 v = *(const float4*)(src + (size_t)i * 4);
        __half2 lo = __floats2half2_rn(v.x, v.y);
        __half2 hi = __floats2half2_rn(v.z, v.w);
        uint2 o;
        o.x = *(uint32_t*)&lo;
        o.y = *(uint32_t*)&hi;
        *(uint2*)(dst + (size_t)i * 4) = o;
    }
}

// ---------------------------------------------------------------------------
// cp.async helpers
// ---------------------------------------------------------------------------
__device__ __forceinline__ uint32_t smem_u32(const void* p) {
    uint32_t a;
    asm("{ .reg .u64 t; cvta.to.shared.u64 t, %1; cvt.u32.u64 %0, t; }" : "=r"(a) : "l"(p));
    return a;
}
#define CP_ASYNC16(dst, src) \
    asm volatile("cp.async.cg.shared.global [%0], [%1], 16;" :: "r"(dst), "l"(src))
#define CP_COMMIT() asm volatile("cp.async.commit_group;")
#define CP_WAIT(N)  asm volatile("cp.async.wait_group %0;" :: "n"(N) : "memory")

// ---------------------------------------------------------------------------
// fp16 GEMM v2: C[M,N] = A[M,K]h @ W[N,K]h^T + bias
// BM=128, BN=256, BK=64, 3-stage cp.async. 8 warps, warp tile 64x64.
// LAYOUT 0: C fp32 row-major [M,N]   LAYOUT 1: C half [B,H,S,hd]
// ---------------------------------------------------------------------------
#define GLD   72                                   // half stride (64 + 8 pad)
#define GBK   64
#define GNST  3
#define GNCH  (DMODEL / GBK)                       // 16
#define GM_ATILE (128 * GLD * 2)                   // 18432
#define GM_BTILE (256 * GLD * 2)                   // 36864
#define GM_STAGE (GM_ATILE + GM_BTILE)             // 55296
#define GEMM_SMEM (GNST * GM_STAGE)                // 165888

template <int LAYOUT>
__global__ void __launch_bounds__(256, 1)
gemm_h_kernel(const __half* __restrict__ A, const __half* __restrict__ W,
              const float* __restrict__ bias, void* __restrict__ Cv)
{
    extern __shared__ __align__(128) char smem[];
    const uint32_t sbase = smem_u32(smem);
    const int tid  = threadIdx.x;
    const int warp = tid >> 5;
    const int wm   = warp & 1;      // 2 row groups of 64
    const int wn   = warp >> 1;     // 4 col groups of 64
    const int m0   = blockIdx.y * 128;
    const int n0   = blockIdx.x * 256;

    const __half* Abase = A + (size_t)m0 * DMODEL;
    const __half* Bbase = W + (size_t)n0 * DMODEL;

    wmma::fragment<wmma::accumulator, 16, 16, 16, float> acc[4][4];
#pragma unroll
    for (int i = 0; i < 4; i++)
#pragma unroll
        for (int j = 0; j < 4; j++)
            wmma::fill_fragment(acc[i][j], 0.0f);

    auto load_stage = [&](int c, int s) {
        const int k0 = c * GBK;
        uint32_t sa = sbase + s * GM_STAGE;
        // A: 128 rows x 8 chunks of 8 halves = 1024 cp.async
#pragma unroll
        for (int i = 0; i < 4; i++) {
            int idx = tid + i * 256;
            int r = idx >> 3, ch = (idx & 7) << 3;
            CP_ASYNC16(sa + (r * GLD + ch) * 2,
                       Abase + (size_t)r * DMODEL + k0 + ch);
        }
        // B: 256 rows x 8 chunks = 2048 cp.async
#pragma unroll
        for (int i = 0; i < 8; i++) {
            int idx = tid + i * 256;
            int r = idx >> 3, ch = (idx & 7) << 3;
            CP_ASYNC16(sa + GM_ATILE + (r * GLD + ch) * 2,
                       Bbase + (size_t)r * DMODEL + k0 + ch);
        }
    };

    load_stage(0, 0); CP_COMMIT();
    load_stage(1, 1); CP_COMMIT();

    for (int c = 0; c < GNCH; c++) {
        const int s = c % GNST;
        CP_WAIT(1);
        __syncthreads();

        if (c + GNST - 1 < GNCH) load_stage(c + GNST - 1, (c + GNST - 1) % GNST);
        CP_COMMIT();

        const __half* As = (const __half*)(smem + s * GM_STAGE);
        const __half* Bs = (const __half*)(smem + s * GM_STAGE + GM_ATILE);
#pragma unroll
        for (int ks = 0; ks < GBK / 16; ks++) {
            wmma::fragment<wmma::matrix_a, 16, 16, 16, __half, wmma::row_major> af[4];
#pragma unroll
            for (int i = 0; i < 4; i++)
                wmma::load_matrix_sync(af[i], As + (wm * 64 + i * 16) * GLD + ks * 16, GLD);
#pragma unroll
            for (int j = 0; j < 4; j++) {
                wmma::fragment<wmma::matrix_b, 16, 16, 16, __half, wmma::col_major> bf;
                wmma::load_matrix_sync(bf, Bs + (wn * 64 + j * 16) * GLD + ks * 16, GLD);
#pragma unroll
                for (int i = 0; i < 4; i++)
                    wmma::mma_sync(acc[i][j], af[i], bf, acc[i][j]);
            }
        }
        __syncthreads();
    }

    CP_WAIT(0);
    __syncthreads();

    // Epilogue in two 128-col halves (staging buffer 128x132 fp32 = 67.6KB)
    float* stg = (float*)smem;
#pragma unroll
    for (int hf = 0; hf < 2; hf++) {
        if ((wn >> 1) == hf) {
#pragma unroll
            for (int i = 0; i < 4; i++)
#pragma unroll
                for (int j = 0; j < 4; j++)
                    wmma::store_matrix_sync(
                        &stg[(wm * 64 + i * 16) * 132 + (wn & 1) * 64 + j * 16],
                        acc[i][j], 132, wmma::mem_row_major);
        }
        __syncthreads();

        const int nb = n0 + hf * 128;
#pragma unroll
        for (int i = 0; i < 16; i++) {
            int idx = tid + i * 256;        // 4096 quads = 128 x 32
            int r   = idx >> 5;
            int c4  = (idx & 31) << 2;
            float4 v = *(float4*)&stg[r * 132 + c4];
            float4 bv = *(const float4*)&bias[nb + c4];
            v.x += bv.x; v.y += bv.y; v.z += bv.z; v.w += bv.w;

            if (LAYOUT == 0) {
                float* C = (float*)Cv;
                *(float4*)&C[(size_t)(m0 + r) * DMODEL + nb + c4] = v;
            } else {
                __half* C = (__half*)Cv;
                int m  = m0 + r;
                int bb = m >> 13;
                int ss = m & (SEQ - 1);
                int nn = nb + c4;
                int hh = nn >> 6;
                int d0 = nn & 63;
                __half2 lo = __floats2half2_rn(v.x, v.y);
                __half2 hi = __floats2half2_rn(v.z, v.w);
                uint2 o; o.x = *(uint32_t*)&lo; o.y = *(uint32_t*)&hi;
                *(uint2*)&C[(((size_t)bb * NHEADS + hh) * SEQ + ss) * HD + d0] = o;
            }
        }
        __syncthreads();
    }
}

// ---------------------------------------------------------------------------
// Streaming fp16 attention (half Q/K/V input). One CTA per (b,h,n).
// ---------------------------------------------------------------------------
#define WKB 64
#define NJ  6
#define SCLD 68
#define PLD  72
#define OFF_PH  (128 * SCLD * 4)
#define OFF_KV  (OFF_PH + 128 * PLD * 2)
#define OFF_RS  (OFF_KV + WKB * PLD * 2)
#define ATTN_SMEM (OFF_RS + 512)

__global__ void __launch_bounds__(256)
attn_kernel(const __half* __restrict__ Q, const __half* __restrict__ K,
            const __half* __restrict__ V, __half* __restrict__ O)
{
    extern __shared__ __align__(128) char smem[];
    float*  Sc   = (float*)smem;                  // [128][68]
    __half* Ph   = (__half*)(smem + OFF_PH);      // [128][72]
    __half* KVh  = (__half*)(smem + OFF_KV);      // [64][72]
    float*  rsum = (float*)(smem + OFF_RS);       // [128]

    const int tid  = threadIdx.x;
    const int warp = tid >> 5;
    const int n    = blockIdx.x & 63;
    const int h    = (blockIdx.x >> 6) & 15;
    const int b    = blockIdx.x >> 10;
    const size_t base = ((size_t)(b * NHEADS + h)) * SEQ * HD;
    const int kbase = (n - 1) * BS;

    // ---- Q (half) -> smem -> fragments ----
    {
        const __half* qb = Q + base + (size_t)(n * BS) * HD;
#pragma unroll
        for (int i = 0; i < 4; i++) {
            int idx = tid + i * 256;             // 1024 jobs: 128 rows x 8 chunks
            int r = idx >> 3, ch = (idx & 7) << 3;
            *(uint4*)(Ph + r * PLD + ch) = *(const uint4*)(qb + (size_t)r * HD + ch);
        }
    }
    __syncthreads();

    wmma::fragment<wmma::matrix_a, 16, 16, 16, __half, wmma::row_major> qf[4];
#pragma unroll
    for (int ks = 0; ks < 4; ks++)
        wmma::load_matrix_sync(qf[ks], Ph + (warp * 16) * PLD + ks * 16, PLD);
    __syncthreads();

    const int qrow = tid >> 1;
    const int par  = tid & 1;
    int klo = qrow;
    if (kbase < 0 && -kbase > klo) klo = -kbase;
    int khi = qrow + 256;
    {
        int lim = SEQ - kbase - 1;
        if (lim < khi) khi = lim;
    }
    float lsum = 0.f;

    wmma::fragment<wmma::accumulator, 16, 16, 16, float> of[4];
#pragma unroll
    for (int dt = 0; dt < 4; dt++) wmma::fill_fragment(of[dt], 0.0f);

    for (int j = 0; j < NJ; j++) {
        const int kblk = kbase + j * WKB;

        // ---- K_j (64x64 half), zero-padded ----
#pragma unroll
        for (int i = 0; i < 2; i++) {
            int idx = tid + i * 256;             // 512 jobs
            int r = idx >> 3, ch = (idx & 7) << 3;
            int kpos = kblk + r;
            uint4 o = make_uint4(0, 0, 0, 0);
            if (kpos >= 0 && kpos < SEQ)
                o = *(const uint4*)(K + base + (size_t)kpos * HD + ch);
            *(uint4*)(KVh + r * PLD + ch) = o;
        }
        __syncthreads();

        // ---- S_j = Q @ K_j^T ----
#pragma unroll
        for (int nt = 0; nt < 4; nt++) {
            wmma::fragment<wmma::accumulator, 16, 16, 16, float> sacc;
            wmma::fill_fragment(sacc, 0.0f);
#pragma unroll
            for (int ks = 0; ks < 4; ks++) {
                wmma::fragment<wmma::matrix_b, 16, 16, 16, __half, wmma::col_major> bf;
                wmma::load_matrix_sync(bf, KVh + (nt * 16) * PLD + ks * 16, PLD);
                wmma::mma_sync(sacc, qf[ks], bf, sacc);
            }
            wmma::store_matrix_sync(&Sc[(warp * 16) * SCLD + nt * 16], sacc,
                                    SCLD, wmma::mem_row_major);
        }
        __syncthreads();

        // ---- exp + mask -> P halves; row sums ----
        {
            float* row = &Sc[qrow * SCLD];
            __half* prow = Ph + qrow * PLD;
            const int c0 = par * 32;
#pragma unroll
            for (int c4 = 0; c4 < 32; c4 += 4) {
                int c = c0 + c4;
                float4 v = *(float4*)&row[c];
                float p0 = 0.f, p1 = 0.f, p2 = 0.f, p3 = 0.f;
                int kk = j * WKB + c;
                if (kk + 0 >= klo && kk + 0 <= khi) p0 = __expf(v.x * 0.125f);
                if (kk + 1 >= klo && kk + 1 <= khi) p1 = __expf(v.y * 0.125f);
                if (kk + 2 >= klo && kk + 2 <= khi) p2 = __expf(v.z * 0.125f);
                if (kk + 3 >= klo && kk + 3 <= khi) p3 = __expf(v.w * 0.125f);
                lsum += p0 + p1 + p2 + p3;
                __half2 lo = __floats2half2_rn(p0, p1);
                __half2 hi = __floats2half2_rn(p2, p3);
                uint2 o; o.x = *(uint32_t*)&lo; o.y = *(uint32_t*)&hi;
                *(uint2*)&prow[c] = o;
            }
        }

        // ---- V_j (64x64 half), zero-padded ----
#pragma unroll
        for (int i = 0; i < 2; i++) {
            int idx = tid + i * 256;
            int r = idx >> 3, ch = (idx & 7) << 3;
            int kpos = kblk + r;
            uint4 o = make_uint4(0, 0, 0, 0);
            if (kpos >= 0 && kpos < SEQ)
                o = *(const uint4*)(V + base + (size_t)kpos * HD + ch);
            *(uint4*)(KVh + r * PLD + ch) = o;
        }
        __syncthreads();

        // ---- O += P_j @ V_j ----
#pragma unroll
        for (int ks = 0; ks < 4; ks++) {
            wmma::fragment<wmma::matrix_a, 16, 16, 16, __half, wmma::row_major> pf;
            wmma::load_matrix_sync(pf, Ph + (warp * 16) * PLD + ks * 16, PLD);
#pragma unroll
            for (int dt = 0; dt < 4; dt++) {
                wmma::fragment<wmma::matrix_b, 16, 16, 16, __half, wmma::row_major> vf;
                wmma::load_matrix_sync(vf, KVh + (ks * 16) * PLD + dt * 16, PLD);
                wmma::mma_sync(of[dt], pf, vf, of[dt]);
            }
        }
        __syncthreads();
    }

    lsum += __shfl_xor_sync(0xFFFFFFFF, lsum, 1);
    if (par == 0) rsum[qrow] = 1.0f / lsum;

#pragma unroll
    for (int dt = 0; dt < 4; dt++)
        wmma::store_matrix_sync(&Sc[(warp * 16) * SCLD + dt * 16], of[dt],
                                SCLD, wmma::mem_row_major);
    __syncthreads();

#pragma unroll
    for (int i = 0; i < 4; i++) {
        int idx = tid + i * 256;
        int r = idx >> 3, ch = (idx & 7) << 3;
        float s = rsum[r];
        float4 f0 = *(float4*)&Sc[r * SCLD + ch];
        float4 f1 = *(float4*)&Sc[r * SCLD + ch + 4];
        __half2 a = __floats2half2_rn(f0.x * s, f0.y * s);
        __half2 bb2 = __floats2half2_rn(f0.z * s, f0.w * s);
        __half2 cc = __floats2half2_rn(f1.x * s, f1.y * s);
        __half2 d = __floats2half2_rn(f1.z * s, f1.w * s);
        uint4 o;
        o.x = *(uint32_t*)&a; o.y = *(uint32_t*)&bb2;
        o.z = *(uint32_t*)&cc; o.w = *(uint32_t*)&d;
        *(uint4*)&O[((size_t)b * SEQ + (size_t)n * BS + r) * DMODEL + h * HD + ch] = o;
    }
}

// ---------------------------------------------------------------------------
// Launch
// ---------------------------------------------------------------------------
extern "C" void kernel_launch(void* const* d_in, const int* in_sizes, int n_in,
                              void* d_out, int out_size)
{
    const float* x  = (const float*)d_in[0];
    const float* Wq = (const float*)d_in[1];
    const float* bq = (const float*)d_in[2];
    const float* Wk = (const float*)d_in[3];
    const float* bk = (const float*)d_in[4];
    const float* Wv = (const float*)d_in[5];
    const float* bv = (const float*)d_in[6];
    const float* Wo = (const float*)d_in[7];
    const float* bo = (const float*)d_in[8];
    float* out = (float*)d_out;

    __half *xh, *wq, *wk, *wv, *wo, *ah, *qp, *kp, *vp;
    cudaGetSymbolAddress((void**)&xh, g_xh);
    cudaGetSymbolAddress((void**)&wq, g_wq);
    cudaGetSymbolAddress((void**)&wk, g_wk);
    cudaGetSymbolAddress((void**)&wv, g_wv);
    cudaGetSymbolAddress((void**)&wo, g_wo);
    cudaGetSymbolAddress((void**)&ah, g_attnh);
    cudaGetSymbolAddress((void**)&qp, g_qh);
    cudaGetSymbolAddress((void**)&kp, g_kh);
    cudaGetSymbolAddress((void**)&vp, g_vh);

    cudaFuncSetAttribute(gemm_h_kernel<0>,
                         cudaFuncAttributeMaxDynamicSharedMemorySize, GEMM_SMEM);
    cudaFuncSetAttribute(gemm_h_kernel<1>,
                         cudaFuncAttributeMaxDynamicSharedMemorySize, GEMM_SMEM);
    cudaFuncSetAttribute(attn_kernel,
                         cudaFuncAttributeMaxDynamicSharedMemorySize, ATTN_SMEM);

    const int XN4 = (BATCH * SEQ * DMODEL) / 4;
    const int WN4 = (DMODEL * DMODEL) / 4;
    f2h_kernel<<<592, 256>>>(x,  xh, XN4);
    f2h_kernel<<<296, 256>>>(Wq, wq, WN4);
    f2h_kernel<<<296, 256>>>(Wk, wk, WN4);
    f2h_kernel<<<296, 256>>>(Wv, wv, WN4);
    f2h_kernel<<<296, 256>>>(Wo, wo, WN4);

    dim3 ggrid(DMODEL / 256, (BATCH * SEQ) / 128);   // (4,128)
    gemm_h_kernel<1><<<ggrid, 256, GEMM_SMEM>>>(xh, wq, bq, qp);
    gemm_h_kernel<1><<<ggrid, 256, GEMM_SMEM>>>(xh, wk, bk, kp);
    gemm_h_kernel<1><<<ggrid, 256, GEMM_SMEM>>>(xh, wv, bv, vp);

    attn_kernel<<<BATCH * NHEADS * NBLK, 256, ATTN_SMEM>>>(qp, kp, vp, ah);

    gemm_h_kernel<0><<<ggrid, 256, GEMM_SMEM>>>(ah, wo, bo, out);
}

// round 8
// speedup vs baseline: 1.1356x; 1.1356x over previous
#include <cuda_runtime.h>
#include <cuda_fp16.h>
#include <mma.h>
#include <cstdint>

using namespace nvcuda;

#define BATCH   2
#define SEQ     8192
#define DMODEL  1024
#define NHEADS  16
#define HD      64
#define NBLK    64
#define BS      128

// ---------------------------------------------------------------------------
// Device scratch
// ---------------------------------------------------------------------------
__device__ __half g_xh[(size_t)BATCH * SEQ * DMODEL];        // fp16 GEMM input
__device__ __half g_wq[(size_t)DMODEL * DMODEL];
__device__ __half g_wk[(size_t)DMODEL * DMODEL];
__device__ __half g_wv[(size_t)DMODEL * DMODEL];
__device__ __half g_wo[(size_t)DMODEL * DMODEL];
__device__ __half g_qh[(size_t)BATCH * NHEADS * SEQ * HD];   // fp16 q/k/v
__device__ __half g_kh[(size_t)BATCH * NHEADS * SEQ * HD];
__device__ __half g_vh[(size_t)BATCH * NHEADS * SEQ * HD];
__device__ __half g_attnh[(size_t)BATCH * SEQ * DMODEL];     // fp16 attn out

// ---------------------------------------------------------------------------
// fp32 -> fp16 conversion
// ---------------------------------------------------------------------------
__global__ void f2h_kernel(const float* __restrict__ src, __half* __restrict__ dst, int n4)
{
    int i = blockIdx.x * blockDim.x + threadIdx.x;
    for (; i < n4; i += gridDim.x * blockDim.x) {
        float4 v = *(const float4*)(src + (size_t)i * 4);
        __half2 lo = __floats2half2_rn(v.x, v.y);
        __half2 hi = __floats2half2_rn(v.z, v.w);
        uint2 o;
        o.x = *(uint32_t*)&lo;
        o.y = *(uint32_t*)&hi;
        *(uint2*)(dst + (size_t)i * 4) = o;
    }
}

// ---------------------------------------------------------------------------
// cp.async helpers
// ---------------------------------------------------------------------------
__device__ __forceinline__ uint32_t smem_u32(const void* p) {
    uint32_t a;
    asm("{ .reg .u64 t; cvta.to.shared.u64 t, %1; cvt.u32.u64 %0, t; }" : "=r"(a) : "l"(p));
    return a;
}
#define CP_ASYNC16(dst, src) \
    asm volatile("cp.async.cg.shared.global [%0], [%1], 16;" :: "r"(dst), "l"(src))
#define CP_COMMIT() asm volatile("cp.async.commit_group;")
#define CP_WAIT(N)  asm volatile("cp.async.wait_group %0;" :: "n"(N) : "memory")

// ---------------------------------------------------------------------------
// fp16 GEMM (round-5/6 proven config): BM=BN=128, BK=64, warp 32x64,
// 3-stage cp.async, 110KB smem, 2 CTAs/SM.
// LAYOUT 0: C fp32 row-major [M,N]   LAYOUT 1: C half [B,H,S,hd]
// ---------------------------------------------------------------------------
#define BKH   64
#define LDH   72
#define NST   3
#define NCH   (DMODEL / BKH)
#define TILE_HBYTES (128 * LDH * 2)
#define STAGE_BYTES (2 * TILE_HBYTES)
#define GEMM_SMEM   (NST * STAGE_BYTES)

template <int LAYOUT>
__global__ void __launch_bounds__(256, 2)
gemm_h_kernel(const __half* __restrict__ A, const __half* __restrict__ W,
              const float* __restrict__ bias, void* __restrict__ Cv)
{
    extern __shared__ __align__(128) char smem[];
    const uint32_t sbase = smem_u32(smem);
    const int tid  = threadIdx.x;
    const int warp = tid >> 5;
    const int wm   = warp & 3;
    const int wn   = warp >> 2;
    const int m0   = blockIdx.y * 128;
    const int n0   = blockIdx.x * 128;

    const __half* Abase = A + (size_t)m0 * DMODEL;
    const __half* Bbase = W + (size_t)n0 * DMODEL;

    wmma::fragment<wmma::accumulator, 16, 16, 16, float> acc[2][4];
#pragma unroll
    for (int i = 0; i < 2; i++)
#pragma unroll
        for (int j = 0; j < 4; j++)
            wmma::fill_fragment(acc[i][j], 0.0f);

    auto load_stage = [&](int c, int s) {
        const int k0 = c * BKH;
        uint32_t sa = sbase + s * STAGE_BYTES;
#pragma unroll
        for (int i = 0; i < 4; i++) {
            int idx = tid + i * 256;
            int r = idx >> 3, ch = (idx & 7) << 3;
            CP_ASYNC16(sa + (r * LDH + ch) * 2,
                       Abase + (size_t)r * DMODEL + k0 + ch);
        }
#pragma unroll
        for (int i = 0; i < 4; i++) {
            int idx = tid + i * 256;
            int r = idx >> 3, ch = (idx & 7) << 3;
            CP_ASYNC16(sa + TILE_HBYTES + (r * LDH + ch) * 2,
                       Bbase + (size_t)r * DMODEL + k0 + ch);
        }
    };

    load_stage(0, 0); CP_COMMIT();
    load_stage(1, 1); CP_COMMIT();

    for (int c = 0; c < NCH; c++) {
        const int s = c % NST;
        CP_WAIT(1);
        __syncthreads();

        if (c + NST - 1 < NCH) load_stage(c + NST - 1, (c + NST - 1) % NST);
        CP_COMMIT();

        const __half* As = (const __half*)(smem + s * STAGE_BYTES);
        const __half* Bs = (const __half*)(smem + s * STAGE_BYTES + TILE_HBYTES);
#pragma unroll
        for (int ks = 0; ks < BKH / 16; ks++) {
            wmma::fragment<wmma::matrix_a, 16, 16, 16, __half, wmma::row_major> af[2];
#pragma unroll
            for (int i = 0; i < 2; i++)
                wmma::load_matrix_sync(af[i], As + (wm * 32 + i * 16) * LDH + ks * 16, LDH);
#pragma unroll
            for (int j = 0; j < 4; j++) {
                wmma::fragment<wmma::matrix_b, 16, 16, 16, __half, wmma::col_major> bf;
                wmma::load_matrix_sync(bf, Bs + (wn * 64 + j * 16) * LDH + ks * 16, LDH);
#pragma unroll
                for (int i = 0; i < 2; i++)
                    wmma::mma_sync(acc[i][j], af[i], bf, acc[i][j]);
            }
        }
        __syncthreads();
    }

    CP_WAIT(0);
    __syncthreads();

    float* stg = (float*)smem;   // 128 x 132 fp32 = 67584 <= 110592
#pragma unroll
    for (int i = 0; i < 2; i++)
#pragma unroll
        for (int j = 0; j < 4; j++)
            wmma::store_matrix_sync(&stg[(wm * 32 + i * 16) * 132 + wn * 64 + j * 16],
                                    acc[i][j], 132, wmma::mem_row_major);
    __syncthreads();

#pragma unroll
    for (int i = 0; i < 16; i++) {
        int idx = tid + i * 256;        // 4096 quads
        int r   = idx >> 5;
        int c4  = (idx & 31) << 2;
        float4 v = *(float4*)&stg[r * 132 + c4];
        float4 bv = *(const float4*)&bias[n0 + c4];
        v.x += bv.x; v.y += bv.y; v.z += bv.z; v.w += bv.w;

        if (LAYOUT == 0) {
            float* C = (float*)Cv;
            *(float4*)&C[(size_t)(m0 + r) * DMODEL + n0 + c4] = v;
        } else {
            __half* C = (__half*)Cv;
            int m  = m0 + r;
            int bb = m >> 13;
            int ss = m & (SEQ - 1);
            int nn = n0 + c4;
            int hh = nn >> 6;
            int d0 = nn & 63;
            __half2 lo = __floats2half2_rn(v.x, v.y);
            __half2 hi = __floats2half2_rn(v.z, v.w);
            uint2 o; o.x = *(uint32_t*)&lo; o.y = *(uint32_t*)&hi;
            *(uint2*)&C[(((size_t)bb * NHEADS + hh) * SEQ + ss) * HD + d0] = o;
        }
    }
}

// ---------------------------------------------------------------------------
// Streaming fp16 attention (half Q/K/V input) — round-7 version (validated).
// ---------------------------------------------------------------------------
#define WKB 64
#define NJ  6
#define SCLD 68
#define PLD  72
#define OFF_PH  (128 * SCLD * 4)
#define OFF_KV  (OFF_PH + 128 * PLD * 2)
#define OFF_RS  (OFF_KV + WKB * PLD * 2)
#define ATTN_SMEM (OFF_RS + 512)

__global__ void __launch_bounds__(256)
attn_kernel(const __half* __restrict__ Q, const __half* __restrict__ K,
            const __half* __restrict__ V, __half* __restrict__ O)
{
    extern __shared__ __align__(128) char smem[];
    float*  Sc   = (float*)smem;                  // [128][68]
    __half* Ph   = (__half*)(smem + OFF_PH);      // [128][72]
    __half* KVh  = (__half*)(smem + OFF_KV);      // [64][72]
    float*  rsum = (float*)(smem + OFF_RS);       // [128]

    const int tid  = threadIdx.x;
    const int warp = tid >> 5;
    const int n    = blockIdx.x & 63;
    const int h    = (blockIdx.x >> 6) & 15;
    const int b    = blockIdx.x >> 10;
    const size_t base = ((size_t)(b * NHEADS + h)) * SEQ * HD;
    const int kbase = (n - 1) * BS;

    // ---- Q (half) -> smem -> fragments ----
    {
        const __half* qb = Q + base + (size_t)(n * BS) * HD;
#pragma unroll
        for (int i = 0; i < 4; i++) {
            int idx = tid + i * 256;             // 1024 jobs: 128 rows x 8 chunks
            int r = idx >> 3, ch = (idx & 7) << 3;
            *(uint4*)(Ph + r * PLD + ch) = *(const uint4*)(qb + (size_t)r * HD + ch);
        }
    }
    __syncthreads();

    wmma::fragment<wmma::matrix_a, 16, 16, 16, __half, wmma::row_major> qf[4];
#pragma unroll
    for (int ks = 0; ks < 4; ks++)
        wmma::load_matrix_sync(qf[ks], Ph + (warp * 16) * PLD + ks * 16, PLD);
    __syncthreads();

    const int qrow = tid >> 1;
    const int par  = tid & 1;
    int klo = qrow;
    if (kbase < 0 && -kbase > klo) klo = -kbase;
    int khi = qrow + 256;
    {
        int lim = SEQ - kbase - 1;
        if (lim < khi) khi = lim;
    }
    float lsum = 0.f;

    wmma::fragment<wmma::accumulator, 16, 16, 16, float> of[4];
#pragma unroll
    for (int dt = 0; dt < 4; dt++) wmma::fill_fragment(of[dt], 0.0f);

    for (int j = 0; j < NJ; j++) {
        const int kblk = kbase + j * WKB;

        // ---- K_j (64x64 half), zero-padded ----
#pragma unroll
        for (int i = 0; i < 2; i++) {
            int idx = tid + i * 256;             // 512 jobs
            int r = idx >> 3, ch = (idx & 7) << 3;
            int kpos = kblk + r;
            uint4 o = make_uint4(0, 0, 0, 0);
            if (kpos >= 0 && kpos < SEQ)
                o = *(const uint4*)(K + base + (size_t)kpos * HD + ch);
            *(uint4*)(KVh + r * PLD + ch) = o;
        }
        __syncthreads();

        // ---- S_j = Q @ K_j^T ----
#pragma unroll
        for (int nt = 0; nt < 4; nt++) {
            wmma::fragment<wmma::accumulator, 16, 16, 16, float> sacc;
            wmma::fill_fragment(sacc, 0.0f);
#pragma unroll
            for (int ks = 0; ks < 4; ks++) {
                wmma::fragment<wmma::matrix_b, 16, 16, 16, __half, wmma::col_major> bf;
                wmma::load_matrix_sync(bf, KVh + (nt * 16) * PLD + ks * 16, PLD);
                wmma::mma_sync(sacc, qf[ks], bf, sacc);
            }
            wmma::store_matrix_sync(&Sc[(warp * 16) * SCLD + nt * 16], sacc,
                                    SCLD, wmma::mem_row_major);
        }
        __syncthreads();

        // ---- exp + mask -> P halves; row sums ----
        {
            float* row = &Sc[qrow * SCLD];
            __half* prow = Ph + qrow * PLD;
            const int c0 = par * 32;
#pragma unroll
            for (int c4 = 0; c4 < 32; c4 += 4) {
                int c = c0 + c4;
                float4 v = *(float4*)&row[c];
                float p0 = 0.f, p1 = 0.f, p2 = 0.f, p3 = 0.f;
                int kk = j * WKB + c;
                if (kk + 0 >= klo && kk + 0 <= khi) p0 = __expf(v.x * 0.125f);
                if (kk + 1 >= klo && kk + 1 <= khi) p1 = __expf(v.y * 0.125f);
                if (kk + 2 >= klo && kk + 2 <= khi) p2 = __expf(v.z * 0.125f);
                if (kk + 3 >= klo && kk + 3 <= khi) p3 = __expf(v.w * 0.125f);
                lsum += p0 + p1 + p2 + p3;
                __half2 lo = __floats2half2_rn(p0, p1);
                __half2 hi = __floats2half2_rn(p2, p3);
                uint2 o; o.x = *(uint32_t*)&lo; o.y = *(uint32_t*)&hi;
                *(uint2*)&prow[c] = o;
            }
        }

        // ---- V_j (64x64 half), zero-padded ----
#pragma unroll
        for (int i = 0; i < 2; i++) {
            int idx = tid + i * 256;
            int r = idx >> 3, ch = (idx & 7) << 3;
            int kpos = kblk + r;
            uint4 o = make_uint4(0, 0, 0, 0);
            if (kpos >= 0 && kpos < SEQ)
                o = *(const uint4*)(V + base + (size_t)kpos * HD + ch);
            *(uint4*)(KVh + r * PLD + ch) = o;
        }
        __syncthreads();

        // ---- O += P_j @ V_j ----
#pragma unroll
        for (int ks = 0; ks < 4; ks++) {
            wmma::fragment<wmma::matrix_a, 16, 16, 16, __half, wmma::row_major> pf;
            wmma::load_matrix_sync(pf, Ph + (warp * 16) * PLD + ks * 16, PLD);
#pragma unroll
            for (int dt = 0; dt < 4; dt++) {
                wmma::fragment<wmma::matrix_b, 16, 16, 16, __half, wmma::row_major> vf;
                wmma::load_matrix_sync(vf, KVh + (ks * 16) * PLD + dt * 16, PLD);
                wmma::mma_sync(of[dt], pf, vf, of[dt]);
            }
        }
        __syncthreads();
    }

    lsum += __shfl_xor_sync(0xFFFFFFFF, lsum, 1);
    if (par == 0) rsum[qrow] = 1.0f / lsum;

#pragma unroll
    for (int dt = 0; dt < 4; dt++)
        wmma::store_matrix_sync(&Sc[(warp * 16) * SCLD + dt * 16], of[dt],
                                SCLD, wmma::mem_row_major);
    __syncthreads();

#pragma unroll
    for (int i = 0; i < 4; i++) {
        int idx = tid + i * 256;
        int r = idx >> 3, ch = (idx & 7) << 3;
        float s = rsum[r];
        float4 f0 = *(float4*)&Sc[r * SCLD + ch];
        float4 f1 = *(float4*)&Sc[r * SCLD + ch + 4];
        __half2 a = __floats2half2_rn(f0.x * s, f0.y * s);
        __half2 bb2 = __floats2half2_rn(f0.z * s, f0.w * s);
        __half2 cc = __floats2half2_rn(f1.x * s, f1.y * s);
        __half2 d = __floats2half2_rn(f1.z * s, f1.w * s);
        uint4 o;
        o.x = *(uint32_t*)&a; o.y = *(uint32_t*)&bb2;
        o.z = *(uint32_t*)&cc; o.w = *(uint32_t*)&d;
        *(uint4*)&O[((size_t)b * SEQ + (size_t)n * BS + r) * DMODEL + h * HD + ch] = o;
    }
}

// ---------------------------------------------------------------------------
// Launch
// ---------------------------------------------------------------------------
extern "C" void kernel_launch(void* const* d_in, const int* in_sizes, int n_in,
                              void* d_out, int out_size)
{
    const float* x  = (const float*)d_in[0];
    const float* Wq = (const float*)d_in[1];
    const float* bq = (const float*)d_in[2];
    const float* Wk = (const float*)d_in[3];
    const float* bk = (const float*)d_in[4];
    const float* Wv = (const float*)d_in[5];
    const float* bv = (const float*)d_in[6];
    const float* Wo = (const float*)d_in[7];
    const float* bo = (const float*)d_in[8];
    float* out = (float*)d_out;

    __half *xh, *wq, *wk, *wv, *wo, *ah, *qp, *kp, *vp;
    cudaGetSymbolAddress((void**)&xh, g_xh);
    cudaGetSymbolAddress((void**)&wq, g_wq);
    cudaGetSymbolAddress((void**)&wk, g_wk);
    cudaGetSymbolAddress((void**)&wv, g_wv);
    cudaGetSymbolAddress((void**)&wo, g_wo);
    cudaGetSymbolAddress((void**)&ah, g_attnh);
    cudaGetSymbolAddress((void**)&qp, g_qh);
    cudaGetSymbolAddress((void**)&kp, g_kh);
    cudaGetSymbolAddress((void**)&vp, g_vh);

    cudaFuncSetAttribute(gemm_h_kernel<0>,
                         cudaFuncAttributeMaxDynamicSharedMemorySize, GEMM_SMEM);
    cudaFuncSetAttribute(gemm_h_kernel<1>,
                         cudaFuncAttributeMaxDynamicSharedMemorySize, GEMM_SMEM);
    cudaFuncSetAttribute(attn_kernel,
                         cudaFuncAttributeMaxDynamicSharedMemorySize, ATTN_SMEM);

    const int XN4 = (BATCH * SEQ * DMODEL) / 4;
    const int WN4 = (DMODEL * DMODEL) / 4;
    f2h_kernel<<<592, 256>>>(x,  xh, XN4);
    f2h_kernel<<<296, 256>>>(Wq, wq, WN4);
    f2h_kernel<<<296, 256>>>(Wk, wk, WN4);
    f2h_kernel<<<296, 256>>>(Wv, wv, WN4);
    f2h_kernel<<<296, 256>>>(Wo, wo, WN4);

    dim3 ggrid(DMODEL / 128, (BATCH * SEQ) / 128);   // (8,128)
    gemm_h_kernel<1><<<ggrid, 256, GEMM_SMEM>>>(xh, wq, bq, qp);
    gemm_h_kernel<1><<<ggrid, 256, GEMM_SMEM>>>(xh, wk, bk, kp);
    gemm_h_kernel<1><<<ggrid, 256, GEMM_SMEM>>>(xh, wv, bv, vp);

    attn_kernel<<<BATCH * NHEADS * NBLK, 256, ATTN_SMEM>>>(qp, kp, vp, ah);

    gemm_h_kernel<0><<<ggrid, 256, GEMM_SMEM>>>(ah, wo, bo, out);
}

// round 9
// speedup vs baseline: 1.1706x; 1.0308x over previous
#include <cuda_runtime.h>
#include <cuda_fp16.h>
#include <mma.h>
#include <cstdint>

using namespace nvcuda;

#define BATCH   2
#define SEQ     8192
#define DMODEL  1024
#define NHEADS  16
#define HD      64
#define NBLK    64
#define BS      128

#define QKV_SEG ((size_t)BATCH * NHEADS * SEQ * HD)   // 16M halves per segment

// ---------------------------------------------------------------------------
// Device scratch
// ---------------------------------------------------------------------------
__device__ __half g_xh[(size_t)BATCH * SEQ * DMODEL];      // fp16 x
__device__ __half g_wqkv[(size_t)3 * DMODEL * DMODEL];     // Wq|Wk|Wv concat (N-dim)
__device__ __half g_wo[(size_t)DMODEL * DMODEL];
__device__ float  g_bqkv[3 * DMODEL];                      // bq|bk|bv concat
__device__ __half g_qkvh[3 * QKV_SEG];                     // q|k|v fp16
__device__ __half g_attnh[(size_t)BATCH * SEQ * DMODEL];   // fp16 attn out

// ---------------------------------------------------------------------------
// conversion kernels
// ---------------------------------------------------------------------------
__global__ void f2h_kernel(const float* __restrict__ src, __half* __restrict__ dst, int n4)
{
    int i = blockIdx.x * blockDim.x + threadIdx.x;
    for (; i < n4; i += gridDim.x * blockDim.x) {
        float4 v = *(const float4*)(src + (size_t)i * 4);
        __half2 lo = __floats2half2_rn(v.x, v.y);
        __half2 hi = __floats2half2_rn(v.z, v.w);
        uint2 o;
        o.x = *(uint32_t*)&lo;
        o.y = *(uint32_t*)&hi;
        *(uint2*)(dst + (size_t)i * 4) = o;
    }
}

// three weights -> concatenated half buffer
__global__ void f2h3_kernel(const float* __restrict__ s0, const float* __restrict__ s1,
                            const float* __restrict__ s2, __half* __restrict__ dst)
{
    const int seg4 = (DMODEL * DMODEL) / 4;   // 262144
    int i = blockIdx.x * blockDim.x + threadIdx.x;
    for (; i < 3 * seg4; i += gridDim.x * blockDim.x) {
        int which = i / seg4;
        int loc = i - which * seg4;
        const float* src = (which == 0) ? s0 : (which == 1) ? s1 : s2;
        float4 v = *(const float4*)(src + (size_t)loc * 4);
        __half2 lo = __floats2half2_rn(v.x, v.y);
        __half2 hi = __floats2half2_rn(v.z, v.w);
        uint2 o;
        o.x = *(uint32_t*)&lo;
        o.y = *(uint32_t*)&hi;
        *(uint2*)(dst + (size_t)i * 4) = o;
    }
}

__global__ void bias3_kernel(const float* __restrict__ b0, const float* __restrict__ b1,
                             const float* __restrict__ b2, float* __restrict__ dst)
{
    int i = blockIdx.x * blockDim.x + threadIdx.x;   // 3072 threads
    if (i < DMODEL)            dst[i] = b0[i];
    else if (i < 2 * DMODEL)   dst[i] = b1[i - DMODEL];
    else if (i < 3 * DMODEL)   dst[i] = b2[i - 2 * DMODEL];
}

// ---------------------------------------------------------------------------
// cp.async helpers
// ---------------------------------------------------------------------------
__device__ __forceinline__ uint32_t smem_u32(const void* p) {
    uint32_t a;
    asm("{ .reg .u64 t; cvta.to.shared.u64 t, %1; cvt.u32.u64 %0, t; }" : "=r"(a) : "l"(p));
    return a;
}
#define CP_ASYNC16(dst, src) \
    asm volatile("cp.async.cg.shared.global [%0], [%1], 16;" :: "r"(dst), "l"(src))
#define CP_COMMIT() asm volatile("cp.async.commit_group;")
#define CP_WAIT(N)  asm volatile("cp.async.wait_group %0;" :: "n"(N) : "memory")

// ---------------------------------------------------------------------------
// fp16 GEMM: BM=BN=128, BK=64, warp 32x64, 3-stage cp.async, 2 CTAs/SM.
// LAYOUT 0: C fp32 row-major [M,N]  (N=1024 out-proj)
// LAYOUT 1: C half, fused QKV: segment by n>>10, then [B,H,S,hd]  (N=3072)
// ---------------------------------------------------------------------------
#define BKH   64
#define LDH   72
#define NST   3
#define NCH   (DMODEL / BKH)
#define TILE_HBYTES (128 * LDH * 2)
#define STAGE_BYTES (2 * TILE_HBYTES)
#define GEMM_SMEM   (NST * STAGE_BYTES)

template <int LAYOUT>
__global__ void __launch_bounds__(256, 2)
gemm_h_kernel(const __half* __restrict__ A, const __half* __restrict__ W,
              const float* __restrict__ bias, void* __restrict__ Cv)
{
    extern __shared__ __align__(128) char smem[];
    const uint32_t sbase = smem_u32(smem);
    const int tid  = threadIdx.x;
    const int warp = tid >> 5;
    const int wm   = warp & 3;
    const int wn   = warp >> 2;
    const int m0   = blockIdx.y * 128;
    const int n0   = blockIdx.x * 128;

    const __half* Abase = A + (size_t)m0 * DMODEL;
    const __half* Bbase = W + (size_t)n0 * DMODEL;

    wmma::fragment<wmma::accumulator, 16, 16, 16, float> acc[2][4];
#pragma unroll
    for (int i = 0; i < 2; i++)
#pragma unroll
        for (int j = 0; j < 4; j++)
            wmma::fill_fragment(acc[i][j], 0.0f);

    auto load_stage = [&](int c, int s) {
        const int k0 = c * BKH;
        uint32_t sa = sbase + s * STAGE_BYTES;
#pragma unroll
        for (int i = 0; i < 4; i++) {
            int idx = tid + i * 256;
            int r = idx >> 3, ch = (idx & 7) << 3;
            CP_ASYNC16(sa + (r * LDH + ch) * 2,
                       Abase + (size_t)r * DMODEL + k0 + ch);
        }
#pragma unroll
        for (int i = 0; i < 4; i++) {
            int idx = tid + i * 256;
            int r = idx >> 3, ch = (idx & 7) << 3;
            CP_ASYNC16(sa + TILE_HBYTES + (r * LDH + ch) * 2,
                       Bbase + (size_t)r * DMODEL + k0 + ch);
        }
    };

    load_stage(0, 0); CP_COMMIT();
    load_stage(1, 1); CP_COMMIT();

    for (int c = 0; c < NCH; c++) {
        const int s = c % NST;
        CP_WAIT(1);
        __syncthreads();

        if (c + NST - 1 < NCH) load_stage(c + NST - 1, (c + NST - 1) % NST);
        CP_COMMIT();

        const __half* As = (const __half*)(smem + s * STAGE_BYTES);
        const __half* Bs = (const __half*)(smem + s * STAGE_BYTES + TILE_HBYTES);
#pragma unroll
        for (int ks = 0; ks < BKH / 16; ks++) {
            wmma::fragment<wmma::matrix_a, 16, 16, 16, __half, wmma::row_major> af[2];
#pragma unroll
            for (int i = 0; i < 2; i++)
                wmma::load_matrix_sync(af[i], As + (wm * 32 + i * 16) * LDH + ks * 16, LDH);
#pragma unroll
            for (int j = 0; j < 4; j++) {
                wmma::fragment<wmma::matrix_b, 16, 16, 16, __half, wmma::col_major> bf;
                wmma::load_matrix_sync(bf, Bs + (wn * 64 + j * 16) * LDH + ks * 16, LDH);
#pragma unroll
                for (int i = 0; i < 2; i++)
                    wmma::mma_sync(acc[i][j], af[i], bf, acc[i][j]);
            }
        }
        // NOTE: no trailing __syncthreads — next iteration's prefetch targets
        // stage (c+3)%3 == c%3 only after the next top-of-loop barrier, which
        // orders all warps past this iteration's reads.
    }

    CP_WAIT(0);
    __syncthreads();

    float* stg = (float*)smem;   // 128 x 132 fp32 = 67584 <= 110592
#pragma unroll
    for (int i = 0; i < 2; i++)
#pragma unroll
        for (int j = 0; j < 4; j++)
            wmma::store_matrix_sync(&stg[(wm * 32 + i * 16) * 132 + wn * 64 + j * 16],
                                    acc[i][j], 132, wmma::mem_row_major);
    __syncthreads();

#pragma unroll
    for (int i = 0; i < 16; i++) {
        int idx = tid + i * 256;        // 4096 quads
        int r   = idx >> 5;
        int c4  = (idx & 31) << 2;
        float4 v = *(float4*)&stg[r * 132 + c4];
        float4 bv = *(const float4*)&bias[n0 + c4];
        v.x += bv.x; v.y += bv.y; v.z += bv.z; v.w += bv.w;

        if (LAYOUT == 0) {
            float* C = (float*)Cv;
            *(float4*)&C[(size_t)(m0 + r) * DMODEL + n0 + c4] = v;
        } else {
            __half* C = (__half*)Cv;
            int m  = m0 + r;
            int bb = m >> 13;
            int ss = m & (SEQ - 1);
            int nn = n0 + c4;
            int which = nn >> 10;            // 0=q 1=k 2=v (uniform per CTA)
            int nl = nn & 1023;
            int hh = nl >> 6;
            int d0 = nl & 63;
            __half2 lo = __floats2half2_rn(v.x, v.y);
            __half2 hi = __floats2half2_rn(v.z, v.w);
            uint2 o; o.x = *(uint32_t*)&lo; o.y = *(uint32_t*)&hi;
            *(uint2*)&C[(size_t)which * QKV_SEG +
                        (((size_t)bb * NHEADS + hh) * SEQ + ss) * HD + d0] = o;
        }
    }
}

// ---------------------------------------------------------------------------
// Streaming fp16 attention (half Q/K/V input) — validated round-8 version.
// ---------------------------------------------------------------------------
#define WKB 64
#define NJ  6
#define SCLD 68
#define PLD  72
#define OFF_PH  (128 * SCLD * 4)
#define OFF_KV  (OFF_PH + 128 * PLD * 2)
#define OFF_RS  (OFF_KV + WKB * PLD * 2)
#define ATTN_SMEM (OFF_RS + 512)

__global__ void __launch_bounds__(256)
attn_kernel(const __half* __restrict__ Q, const __half* __restrict__ K,
            const __half* __restrict__ V, __half* __restrict__ O)
{
    extern __shared__ __align__(128) char smem[];
    float*  Sc   = (float*)smem;                  // [128][68]
    __half* Ph   = (__half*)(smem + OFF_PH);      // [128][72]
    __half* KVh  = (__half*)(smem + OFF_KV);      // [64][72]
    float*  rsum = (float*)(smem + OFF_RS);       // [128]

    const int tid  = threadIdx.x;
    const int warp = tid >> 5;
    const int n    = blockIdx.x & 63;
    const int h    = (blockIdx.x >> 6) & 15;
    const int b    = blockIdx.x >> 10;
    const size_t base = ((size_t)(b * NHEADS + h)) * SEQ * HD;
    const int kbase = (n - 1) * BS;

    {
        const __half* qb = Q + base + (size_t)(n * BS) * HD;
#pragma unroll
        for (int i = 0; i < 4; i++) {
            int idx = tid + i * 256;
            int r = idx >> 3, ch = (idx & 7) << 3;
            *(uint4*)(Ph + r * PLD + ch) = *(const uint4*)(qb + (size_t)r * HD + ch);
        }
    }
    __syncthreads();

    wmma::fragment<wmma::matrix_a, 16, 16, 16, __half, wmma::row_major> qf[4];
#pragma unroll
    for (int ks = 0; ks < 4; ks++)
        wmma::load_matrix_sync(qf[ks], Ph + (warp * 16) * PLD + ks * 16, PLD);
    __syncthreads();

    const int qrow = tid >> 1;
    const int par  = tid & 1;
    int klo = qrow;
    if (kbase < 0 && -kbase > klo) klo = -kbase;
    int khi = qrow + 256;
    {
        int lim = SEQ - kbase - 1;
        if (lim < khi) khi = lim;
    }
    float lsum = 0.f;

    wmma::fragment<wmma::accumulator, 16, 16, 16, float> of[4];
#pragma unroll
    for (int dt = 0; dt < 4; dt++) wmma::fill_fragment(of[dt], 0.0f);

    for (int j = 0; j < NJ; j++) {
        const int kblk = kbase + j * WKB;

#pragma unroll
        for (int i = 0; i < 2; i++) {
            int idx = tid + i * 256;
            int r = idx >> 3, ch = (idx & 7) << 3;
            int kpos = kblk + r;
            uint4 o = make_uint4(0, 0, 0, 0);
            if (kpos >= 0 && kpos < SEQ)
                o = *(const uint4*)(K + base + (size_t)kpos * HD + ch);
            *(uint4*)(KVh + r * PLD + ch) = o;
        }
        __syncthreads();

#pragma unroll
        for (int nt = 0; nt < 4; nt++) {
            wmma::fragment<wmma::accumulator, 16, 16, 16, float> sacc;
            wmma::fill_fragment(sacc, 0.0f);
#pragma unroll
            for (int ks = 0; ks < 4; ks++) {
                wmma::fragment<wmma::matrix_b, 16, 16, 16, __half, wmma::col_major> bf;
                wmma::load_matrix_sync(bf, KVh + (nt * 16) * PLD + ks * 16, PLD);
                wmma::mma_sync(sacc, qf[ks], bf, sacc);
            }
            wmma::store_matrix_sync(&Sc[(warp * 16) * SCLD + nt * 16], sacc,
                                    SCLD, wmma::mem_row_major);
        }
        __syncthreads();

        {
            float* row = &Sc[qrow * SCLD];
            __half* prow = Ph + qrow * PLD;
            const int c0 = par * 32;
#pragma unroll
            for (int c4 = 0; c4 < 32; c4 += 4) {
                int c = c0 + c4;
                float4 v = *(float4*)&row[c];
                float p0 = 0.f, p1 = 0.f, p2 = 0.f, p3 = 0.f;
                int kk = j * WKB + c;
                if (kk + 0 >= klo && kk + 0 <= khi) p0 = __expf(v.x * 0.125f);
                if (kk + 1 >= klo && kk + 1 <= khi) p1 = __expf(v.y * 0.125f);
                if (kk + 2 >= klo && kk + 2 <= khi) p2 = __expf(v.z * 0.125f);
                if (kk + 3 >= klo && kk + 3 <= khi) p3 = __expf(v.w * 0.125f);
                lsum += p0 + p1 + p2 + p3;
                __half2 lo = __floats2half2_rn(p0, p1);
                __half2 hi = __floats2half2_rn(p2, p3);
                uint2 o; o.x = *(uint32_t*)&lo; o.y = *(uint32_t*)&hi;
                *(uint2*)&prow[c] = o;
            }
        }

#pragma unroll
        for (int i = 0; i < 2; i++) {
            int idx = tid + i * 256;
            int r = idx >> 3, ch = (idx & 7) << 3;
            int kpos = kblk + r;
            uint4 o = make_uint4(0, 0, 0, 0);
            if (kpos >= 0 && kpos < SEQ)
                o = *(const uint4*)(V + base + (size_t)kpos * HD + ch);
            *(uint4*)(KVh + r * PLD + ch) = o;
        }
        __syncthreads();

#pragma unroll
        for (int ks = 0; ks < 4; ks++) {
            wmma::fragment<wmma::matrix_a, 16, 16, 16, __half, wmma::row_major> pf;
            wmma::load_matrix_sync(pf, Ph + (warp * 16) * PLD + ks * 16, PLD);
#pragma unroll
            for (int dt = 0; dt < 4; dt++) {
                wmma::fragment<wmma::matrix_b, 16, 16, 16, __half, wmma::row_major> vf;
                wmma::load_matrix_sync(vf, KVh + (ks * 16) * PLD + dt * 16, PLD);
                wmma::mma_sync(of[dt], pf, vf, of[dt]);
            }
        }
        __syncthreads();
    }

    lsum += __shfl_xor_sync(0xFFFFFFFF, lsum, 1);
    if (par == 0) rsum[qrow] = 1.0f / lsum;

#pragma unroll
    for (int dt = 0; dt < 4; dt++)
        wmma::store_matrix_sync(&Sc[(warp * 16) * SCLD + dt * 16], of[dt],
                                SCLD, wmma::mem_row_major);
    __syncthreads();

#pragma unroll
    for (int i = 0; i < 4; i++) {
        int idx = tid + i * 256;
        int r = idx >> 3, ch = (idx & 7) << 3;
        float s = rsum[r];
        float4 f0 = *(float4*)&Sc[r * SCLD + ch];
        float4 f1 = *(float4*)&Sc[r * SCLD + ch + 4];
        __half2 a = __floats2half2_rn(f0.x * s, f0.y * s);
        __half2 bb2 = __floats2half2_rn(f0.z * s, f0.w * s);
        __half2 cc = __floats2half2_rn(f1.x * s, f1.y * s);
        __half2 d = __floats2half2_rn(f1.z * s, f1.w * s);
        uint4 o;
        o.x = *(uint32_t*)&a; o.y = *(uint32_t*)&bb2;
        o.z = *(uint32_t*)&cc; o.w = *(uint32_t*)&d;
        *(uint4*)&O[((size_t)b * SEQ + (size_t)n * BS + r) * DMODEL + h * HD + ch] = o;
    }
}

// ---------------------------------------------------------------------------
// Launch
// ---------------------------------------------------------------------------
extern "C" void kernel_launch(void* const* d_in, const int* in_sizes, int n_in,
                              void* d_out, int out_size)
{
    const float* x  = (const float*)d_in[0];
    const float* Wq = (const float*)d_in[1];
    const float* bq = (const float*)d_in[2];
    const float* Wk = (const float*)d_in[3];
    const float* bk = (const float*)d_in[4];
    const float* Wv = (const float*)d_in[5];
    const float* bv = (const float*)d_in[6];
    const float* Wo = (const float*)d_in[7];
    const float* bo = (const float*)d_in[8];
    float* out = (float*)d_out;

    __half *xh, *wqkv, *wo, *ah, *qkv;
    float  *bqkv;
    cudaGetSymbolAddress((void**)&xh,   g_xh);
    cudaGetSymbolAddress((void**)&wqkv, g_wqkv);
    cudaGetSymbolAddress((void**)&wo,   g_wo);
    cudaGetSymbolAddress((void**)&bqkv, g_bqkv);
    cudaGetSymbolAddress((void**)&ah,   g_attnh);
    cudaGetSymbolAddress((void**)&qkv,  g_qkvh);

    cudaFuncSetAttribute(gemm_h_kernel<0>,
                         cudaFuncAttributeMaxDynamicSharedMemorySize, GEMM_SMEM);
    cudaFuncSetAttribute(gemm_h_kernel<1>,
                         cudaFuncAttributeMaxDynamicSharedMemorySize, GEMM_SMEM);
    cudaFuncSetAttribute(attn_kernel,
                         cudaFuncAttributeMaxDynamicSharedMemorySize, ATTN_SMEM);

    const int XN4 = (BATCH * SEQ * DMODEL) / 4;
    const int WN4 = (DMODEL * DMODEL) / 4;
    f2h_kernel<<<592, 256>>>(x, xh, XN4);
    f2h3_kernel<<<888, 256>>>(Wq, Wk, Wv, wqkv);
    f2h_kernel<<<296, 256>>>(Wo, wo, WN4);
    bias3_kernel<<<12, 256>>>(bq, bk, bv, bqkv);

    // Fused QKV projection: N = 3072
    dim3 qgrid(3 * DMODEL / 128, (BATCH * SEQ) / 128);   // (24,128)
    gemm_h_kernel<1><<<qgrid, 256, GEMM_SMEM>>>(xh, wqkv, bqkv, qkv);

    attn_kernel<<<BATCH * NHEADS * NBLK, 256, ATTN_SMEM>>>(
        qkv, qkv + QKV_SEG, qkv + 2 * QKV_SEG, ah);

    dim3 ogrid(DMODEL / 128, (BATCH * SEQ) / 128);       // (8,128)
    gemm_h_kernel<0><<<ogrid, 256, GEMM_SMEM>>>(ah, wo, bo, out);
}

// round 10
// speedup vs baseline: 1.2236x; 1.0453x over previous
#include <cuda_runtime.h>
#include <cuda_fp16.h>
#include <mma.h>
#include <cstdint>

using namespace nvcuda;

#define BATCH   2
#define SEQ     8192
#define DMODEL  1024
#define NHEADS  16
#define HD      64
#define NBLK    64
#define BS      128

#define QKV_SEG ((size_t)BATCH * NHEADS * SEQ * HD)   // 16M halves per segment

// ---------------------------------------------------------------------------
// Device scratch
// ---------------------------------------------------------------------------
__device__ __half g_xh[(size_t)BATCH * SEQ * DMODEL];      // fp16 x
__device__ __half g_wqkv[(size_t)3 * DMODEL * DMODEL];     // Wq|Wk|Wv concat (N-dim)
__device__ __half g_wo[(size_t)DMODEL * DMODEL];
__device__ __half g_qkvh[3 * QKV_SEG];                     // q|k|v fp16
__device__ __half g_attnh[(size_t)BATCH * SEQ * DMODEL];   // fp16 attn out

// ---------------------------------------------------------------------------
// conversion kernels
// ---------------------------------------------------------------------------
__global__ void f2h_kernel(const float* __restrict__ src, __half* __restrict__ dst, int n4)
{
    int i = blockIdx.x * blockDim.x + threadIdx.x;
    for (; i < n4; i += gridDim.x * blockDim.x) {
        float4 v = *(const float4*)(src + (size_t)i * 4);
        __half2 lo = __floats2half2_rn(v.x, v.y);
        __half2 hi = __floats2half2_rn(v.z, v.w);
        uint2 o;
        o.x = *(uint32_t*)&lo;
        o.y = *(uint32_t*)&hi;
        *(uint2*)(dst + (size_t)i * 4) = o;
    }
}

__global__ void f2h3_kernel(const float* __restrict__ s0, const float* __restrict__ s1,
                            const float* __restrict__ s2, __half* __restrict__ dst)
{
    const int seg4 = (DMODEL * DMODEL) / 4;   // 262144
    int i = blockIdx.x * blockDim.x + threadIdx.x;
    for (; i < 3 * seg4; i += gridDim.x * blockDim.x) {
        int which = i / seg4;
        int loc = i - which * seg4;
        const float* src = (which == 0) ? s0 : (which == 1) ? s1 : s2;
        float4 v = *(const float4*)(src + (size_t)loc * 4);
        __half2 lo = __floats2half2_rn(v.x, v.y);
        __half2 hi = __floats2half2_rn(v.z, v.w);
        uint2 o;
        o.x = *(uint32_t*)&lo;
        o.y = *(uint32_t*)&hi;
        *(uint2*)(dst + (size_t)i * 4) = o;
    }
}

// ---------------------------------------------------------------------------
// cp.async helpers
// ---------------------------------------------------------------------------
__device__ __forceinline__ uint32_t smem_u32(const void* p) {
    uint32_t a;
    asm("{ .reg .u64 t; cvta.to.shared.u64 t, %1; cvt.u32.u64 %0, t; }" : "=r"(a) : "l"(p));
    return a;
}
#define CP_ASYNC16(dst, src) \
    asm volatile("cp.async.cg.shared.global [%0], [%1], 16;" :: "r"(dst), "l"(src))
#define CP_ASYNC16Z(dst, src, sz) \
    asm volatile("cp.async.cg.shared.global [%0], [%1], 16, %2;" :: "r"(dst), "l"(src), "r"(sz))
#define CP_COMMIT() asm volatile("cp.async.commit_group;")
#define CP_WAIT(N)  asm volatile("cp.async.wait_group %0;" :: "n"(N) : "memory")

// ---------------------------------------------------------------------------
// fp16 GEMM (proven config): BM=BN=128, BK=64, warp 32x64, 3-stage, 2 CTAs/SM.
// LAYOUT 0: C fp32 row-major [M,N] (N=1024), bias = b0
// LAYOUT 1: C half, fused QKV (N=3072), bias segment from b0/b1/b2
// ---------------------------------------------------------------------------
#define BKH   64
#define LDH   72
#define NST   3
#define NCH   (DMODEL / BKH)
#define TILE_HBYTES (128 * LDH * 2)
#define STAGE_BYTES (2 * TILE_HBYTES)
#define GEMM_SMEM   (NST * STAGE_BYTES)

template <int LAYOUT>
__global__ void __launch_bounds__(256, 2)
gemm_h_kernel(const __half* __restrict__ A, const __half* __restrict__ W,
              const float* __restrict__ b0, const float* __restrict__ b1,
              const float* __restrict__ b2, void* __restrict__ Cv)
{
    extern __shared__ __align__(128) char smem[];
    const uint32_t sbase = smem_u32(smem);
    const int tid  = threadIdx.x;
    const int warp = tid >> 5;
    const int wm   = warp & 3;
    const int wn   = warp >> 2;
    const int m0   = blockIdx.y * 128;
    const int n0   = blockIdx.x * 128;

    const __half* Abase = A + (size_t)m0 * DMODEL;
    const __half* Bbase = W + (size_t)n0 * DMODEL;

    wmma::fragment<wmma::accumulator, 16, 16, 16, float> acc[2][4];
#pragma unroll
    for (int i = 0; i < 2; i++)
#pragma unroll
        for (int j = 0; j < 4; j++)
            wmma::fill_fragment(acc[i][j], 0.0f);

    auto load_stage = [&](int c, int s) {
        const int k0 = c * BKH;
        uint32_t sa = sbase + s * STAGE_BYTES;
#pragma unroll
        for (int i = 0; i < 4; i++) {
            int idx = tid + i * 256;
            int r = idx >> 3, ch = (idx & 7) << 3;
            CP_ASYNC16(sa + (r * LDH + ch) * 2,
                       Abase + (size_t)r * DMODEL + k0 + ch);
        }
#pragma unroll
        for (int i = 0; i < 4; i++) {
            int idx = tid + i * 256;
            int r = idx >> 3, ch = (idx & 7) << 3;
            CP_ASYNC16(sa + TILE_HBYTES + (r * LDH + ch) * 2,
                       Bbase + (size_t)r * DMODEL + k0 + ch);
        }
    };

    load_stage(0, 0); CP_COMMIT();
    load_stage(1, 1); CP_COMMIT();

    for (int c = 0; c < NCH; c++) {
        const int s = c % NST;
        CP_WAIT(1);
        __syncthreads();

        if (c + NST - 1 < NCH) load_stage(c + NST - 1, (c + NST - 1) % NST);
        CP_COMMIT();

        const __half* As = (const __half*)(smem + s * STAGE_BYTES);
        const __half* Bs = (const __half*)(smem + s * STAGE_BYTES + TILE_HBYTES);
#pragma unroll
        for (int ks = 0; ks < BKH / 16; ks++) {
            wmma::fragment<wmma::matrix_a, 16, 16, 16, __half, wmma::row_major> af[2];
#pragma unroll
            for (int i = 0; i < 2; i++)
                wmma::load_matrix_sync(af[i], As + (wm * 32 + i * 16) * LDH + ks * 16, LDH);
#pragma unroll
            for (int j = 0; j < 4; j++) {
                wmma::fragment<wmma::matrix_b, 16, 16, 16, __half, wmma::col_major> bf;
                wmma::load_matrix_sync(bf, Bs + (wn * 64 + j * 16) * LDH + ks * 16, LDH);
#pragma unroll
                for (int i = 0; i < 2; i++)
                    wmma::mma_sync(acc[i][j], af[i], bf, acc[i][j]);
            }
        }
    }

    CP_WAIT(0);
    __syncthreads();

    float* stg = (float*)smem;   // 128 x 132 fp32
#pragma unroll
    for (int i = 0; i < 2; i++)
#pragma unroll
        for (int j = 0; j < 4; j++)
            wmma::store_matrix_sync(&stg[(wm * 32 + i * 16) * 132 + wn * 64 + j * 16],
                                    acc[i][j], 132, wmma::mem_row_major);
    __syncthreads();

    // bias pointer + segment (uniform per CTA for LAYOUT 1: n0 is 128-aligned)
    const int which = n0 >> 10;
    const float* bp = (LAYOUT == 0) ? b0
                      : (which == 0 ? b0 : (which == 1 ? b1 : b2));
    const int nseg = (LAYOUT == 0) ? n0 : (n0 & 1023);

#pragma unroll
    for (int i = 0; i < 16; i++) {
        int idx = tid + i * 256;        // 4096 quads
        int r   = idx >> 5;
        int c4  = (idx & 31) << 2;
        float4 v = *(float4*)&stg[r * 132 + c4];
        float4 bv = *(const float4*)&bp[nseg + c4];
        v.x += bv.x; v.y += bv.y; v.z += bv.z; v.w += bv.w;

        if (LAYOUT == 0) {
            float* C = (float*)Cv;
            *(float4*)&C[(size_t)(m0 + r) * DMODEL + n0 + c4] = v;
        } else {
            __half* C = (__half*)Cv;
            int m  = m0 + r;
            int bb = m >> 13;
            int ss = m & (SEQ - 1);
            int nl = nseg + c4;
            int hh = nl >> 6;
            int d0 = nl & 63;
            __half2 lo = __floats2half2_rn(v.x, v.y);
            __half2 hi = __floats2half2_rn(v.z, v.w);
            uint2 o; o.x = *(uint32_t*)&lo; o.y = *(uint32_t*)&hi;
            *(uint2*)&C[(size_t)which * QKV_SEG +
                        (((size_t)bb * NHEADS + hh) * SEQ + ss) * HD + d0] = o;
        }
    }
}

// ---------------------------------------------------------------------------
// Pipelined streaming fp16 attention: cp.async double-buffered K/V,
// 1 __syncthreads per key-block, within-warp softmax dependencies.
// SMEM 90.6KB: Sc[128][68] f32 | Ph[128][72] h | KVbuf[2]{K[64][72]+V[64][72]} | rsum
// ---------------------------------------------------------------------------
#define WKB 64
#define NJ  6
#define SCLD 68
#define PLD  72
#define KVLD 72
#define KVBUF_BYTES (2 * WKB * KVLD * 2)          // 18432 (K + V for one block)
#define OFF_PH  (128 * SCLD * 4)                  // 34816
#define OFF_KV0 (OFF_PH + 128 * PLD * 2)          // 53248
#define OFF_KV1 (OFF_KV0 + KVBUF_BYTES)           // 71680
#define OFF_RS  (OFF_KV1 + KVBUF_BYTES)           // 90112
#define ATTN_SMEM (OFF_RS + 512)                  // 90624

__global__ void __launch_bounds__(256)
attn_kernel(const __half* __restrict__ Q, const __half* __restrict__ K,
            const __half* __restrict__ V, __half* __restrict__ O)
{
    extern __shared__ __align__(128) char smem[];
    const uint32_t sbase = smem_u32(smem);
    float*  Sc   = (float*)smem;                  // [128][68]
    __half* Ph   = (__half*)(smem + OFF_PH);      // [128][72]
    float*  rsum = (float*)(smem + OFF_RS);       // [128]

    const int tid  = threadIdx.x;
    const int warp = tid >> 5;
    const int n    = blockIdx.x & 63;
    const int h    = (blockIdx.x >> 6) & 15;
    const int b    = blockIdx.x >> 10;
    const size_t base = ((size_t)(b * NHEADS + h)) * SEQ * HD;
    const int kbase = (n - 1) * BS;

    // issue K_j/V_j loads into buffer parity p (zero-fill OOB rows)
    auto load_kv = [&](int j, uint32_t koff) {
        const int kblk = kbase + j * WKB;
#pragma unroll
        for (int i = 0; i < 2; i++) {
            int idx = tid + i * 256;             // 512 jobs: 64 rows x 8 chunks
            int r = idx >> 3, ch = (idx & 7) << 3;
            int kpos = kblk + r;
            bool ok = (kpos >= 0 && kpos < SEQ);
            uint32_t sz = ok ? 16u : 0u;
            size_t off = ok ? (base + (size_t)kpos * HD + ch) : base;
            CP_ASYNC16Z(koff + (r * KVLD + ch) * 2, K + off, sz);
            CP_ASYNC16Z(koff + WKB * KVLD * 2 + (r * KVLD + ch) * 2, V + off, sz);
        }
    };

    // ---- Q (half) -> smem -> fragments ----
    {
        const __half* qb = Q + base + (size_t)(n * BS) * HD;
#pragma unroll
        for (int i = 0; i < 4; i++) {
            int idx = tid + i * 256;
            int r = idx >> 3, ch = (idx & 7) << 3;
            *(uint4*)(Ph + r * PLD + ch) = *(const uint4*)(qb + (size_t)r * HD + ch);
        }
    }
    __syncthreads();

    wmma::fragment<wmma::matrix_a, 16, 16, 16, __half, wmma::row_major> qf[4];
#pragma unroll
    for (int ks = 0; ks < 4; ks++)
        wmma::load_matrix_sync(qf[ks], Ph + (warp * 16) * PLD + ks * 16, PLD);
    __syncthreads();   // Ph free for P reuse

    const int qrow = tid >> 1;
    const int par  = tid & 1;
    int klo = qrow;
    if (kbase < 0 && -kbase > klo) klo = -kbase;
    int khi = qrow + 256;
    {
        int lim = SEQ - kbase - 1;
        if (lim < khi) khi = lim;
    }
    float lsum = 0.f;

    wmma::fragment<wmma::accumulator, 16, 16, 16, float> of[4];
#pragma unroll
    for (int dt = 0; dt < 4; dt++) wmma::fill_fragment(of[dt], 0.0f);

    // prologue: block 0 in flight
    load_kv(0, sbase + OFF_KV0);
    CP_COMMIT();

    for (int j = 0; j < NJ; j++) {
        const uint32_t koff = sbase + ((j & 1) ? OFF_KV1 : OFF_KV0);

        CP_WAIT(0);          // block j landed (only pending group)
        __syncthreads();     // all warps past prior reads of the other buffer

        if (j + 1 < NJ) {    // prefetch j+1 into the other buffer (overlaps compute)
            load_kv(j + 1, sbase + (((j + 1) & 1) ? OFF_KV1 : OFF_KV0));
            CP_COMMIT();
        }

        const __half* Kb = (const __half*)(smem + (koff - sbase));
        const __half* Vb = Kb + WKB * KVLD;

        // ---- S_j = Q @ K_j^T (warp w -> score rows 16w..16w+15) ----
#pragma unroll
        for (int nt = 0; nt < 4; nt++) {
            wmma::fragment<wmma::accumulator, 16, 16, 16, float> sacc;
            wmma::fill_fragment(sacc, 0.0f);
#pragma unroll
            for (int ks = 0; ks < 4; ks++) {
                wmma::fragment<wmma::matrix_b, 16, 16, 16, __half, wmma::col_major> bf;
                wmma::load_matrix_sync(bf, Kb + (nt * 16) * KVLD + ks * 16, KVLD);
                wmma::mma_sync(sacc, qf[ks], bf, sacc);
            }
            wmma::store_matrix_sync(&Sc[(warp * 16) * SCLD + nt * 16], sacc,
                                    SCLD, wmma::mem_row_major);
        }
        __syncwarp();        // S rows are own-warp; exp reads own-warp rows

        // ---- exp + mask -> P halves; row sums (row qrow = tid>>1 in own warp stripe)
        {
            float* row = &Sc[qrow * SCLD];
            __half* prow = Ph + qrow * PLD;
            const int c0 = par * 32;
#pragma unroll
            for (int c4 = 0; c4 < 32; c4 += 4) {
                int c = c0 + c4;
                float4 v = *(float4*)&row[c];
                float p0 = 0.f, p1 = 0.f, p2 = 0.f, p3 = 0.f;
                int kk = j * WKB + c;
                if (kk + 0 >= klo && kk + 0 <= khi) p0 = __expf(v.x * 0.125f);
                if (kk + 1 >= klo && kk + 1 <= khi) p1 = __expf(v.y * 0.125f);
                if (kk + 2 >= klo && kk + 2 <= khi) p2 = __expf(v.z * 0.125f);
                if (kk + 3 >= klo && kk + 3 <= khi) p3 = __expf(v.w * 0.125f);
                lsum += p0 + p1 + p2 + p3;
                __half2 lo = __floats2half2_rn(p0, p1);
                __half2 hi = __floats2half2_rn(p2, p3);
                uint2 o; o.x = *(uint32_t*)&lo; o.y = *(uint32_t*)&hi;
                *(uint2*)&prow[c] = o;
            }
        }
        __syncwarp();        // P rows are own-warp; pf reads own-warp rows

        // ---- O += P_j @ V_j ----
#pragma unroll
        for (int ks = 0; ks < 4; ks++) {
            wmma::fragment<wmma::matrix_a, 16, 16, 16, __half, wmma::row_major> pf;
            wmma::load_matrix_sync(pf, Ph + (warp * 16) * PLD + ks * 16, PLD);
#pragma unroll
            for (int dt = 0; dt < 4; dt++) {
                wmma::fragment<wmma::matrix_b, 16, 16, 16, __half, wmma::row_major> vf;
                wmma::load_matrix_sync(vf, Vb + (ks * 16) * KVLD + dt * 16, KVLD);
                wmma::mma_sync(of[dt], pf, vf, of[dt]);
            }
        }
        // no trailing barrier: next iteration's top __syncthreads orders
        // buffer reuse against these reads.
    }

    lsum += __shfl_xor_sync(0xFFFFFFFF, lsum, 1);
    if (par == 0) rsum[qrow] = 1.0f / lsum;

#pragma unroll
    for (int dt = 0; dt < 4; dt++)
        wmma::store_matrix_sync(&Sc[(warp * 16) * SCLD + dt * 16], of[dt],
                                SCLD, wmma::mem_row_major);
    __syncthreads();

#pragma unroll
    for (int i = 0; i < 4; i++) {
        int idx = tid + i * 256;
        int r = idx >> 3, ch = (idx & 7) << 3;
        float s = rsum[r];
        float4 f0 = *(float4*)&Sc[r * SCLD + ch];
        float4 f1 = *(float4*)&Sc[r * SCLD + ch + 4];
        __half2 a = __floats2half2_rn(f0.x * s, f0.y * s);
        __half2 bb2 = __floats2half2_rn(f0.z * s, f0.w * s);
        __half2 cc = __floats2half2_rn(f1.x * s, f1.y * s);
        __half2 d = __floats2half2_rn(f1.z * s, f1.w * s);
        uint4 o;
        o.x = *(uint32_t*)&a; o.y = *(uint32_t*)&bb2;
        o.z = *(uint32_t*)&cc; o.w = *(uint32_t*)&d;
        *(uint4*)&O[((size_t)b * SEQ + (size_t)n * BS + r) * DMODEL + h * HD + ch] = o;
    }
}

// ---------------------------------------------------------------------------
// Launch
// ---------------------------------------------------------------------------
extern "C" void kernel_launch(void* const* d_in, const int* in_sizes, int n_in,
                              void* d_out, int out_size)
{
    const float* x  = (const float*)d_in[0];
    const float* Wq = (const float*)d_in[1];
    const float* bq = (const float*)d_in[2];
    const float* Wk = (const float*)d_in[3];
    const float* bk = (const float*)d_in[4];
    const float* Wv = (const float*)d_in[5];
    const float* bv = (const float*)d_in[6];
    const float* Wo = (const float*)d_in[7];
    const float* bo = (const float*)d_in[8];
    float* out = (float*)d_out;

    __half *xh, *wqkv, *wo, *ah, *qkv;
    cudaGetSymbolAddress((void**)&xh,   g_xh);
    cudaGetSymbolAddress((void**)&wqkv, g_wqkv);
    cudaGetSymbolAddress((void**)&wo,   g_wo);
    cudaGetSymbolAddress((void**)&ah,   g_attnh);
    cudaGetSymbolAddress((void**)&qkv,  g_qkvh);

    cudaFuncSetAttribute(gemm_h_kernel<0>,
                         cudaFuncAttributeMaxDynamicSharedMemorySize, GEMM_SMEM);
    cudaFuncSetAttribute(gemm_h_kernel<1>,
                         cudaFuncAttributeMaxDynamicSharedMemorySize, GEMM_SMEM);
    cudaFuncSetAttribute(attn_kernel,
                         cudaFuncAttributeMaxDynamicSharedMemorySize, ATTN_SMEM);

    const int XN4 = (BATCH * SEQ * DMODEL) / 4;
    const int WN4 = (DMODEL * DMODEL) / 4;
    f2h_kernel<<<1184, 256>>>(x, xh, XN4);
    f2h3_kernel<<<1184, 256>>>(Wq, Wk, Wv, wqkv);
    f2h_kernel<<<592, 256>>>(Wo, wo, WN4);

    // Fused QKV projection: N = 3072
    dim3 qgrid(3 * DMODEL / 128, (BATCH * SEQ) / 128);   // (24,128)
    gemm_h_kernel<1><<<qgrid, 256, GEMM_SMEM>>>(xh, wqkv, bq, bk, bv, qkv);

    attn_kernel<<<BATCH * NHEADS * NBLK, 256, ATTN_SMEM>>>(
        qkv, qkv + QKV_SEG, qkv + 2 * QKV_SEG, ah);

    dim3 ogrid(DMODEL / 128, (BATCH * SEQ) / 128);       // (8,128)
    gemm_h_kernel<0><<<ogrid, 256, GEMM_SMEM>>>(ah, wo, bo, bo, bo, out);
}

// round 11
// speedup vs baseline: 1.2513x; 1.0227x over previous
#include <cuda_runtime.h>
#include <cuda_fp16.h>
#include <mma.h>
#include <cstdint>

using namespace nvcuda;

#define BATCH   2
#define SEQ     8192
#define DMODEL  1024
#define NHEADS  16
#define HD      64
#define NBLK    64
#define BS      128

#define QKV_SEG ((size_t)BATCH * NHEADS * SEQ * HD)   // 16M halves per segment

// ---------------------------------------------------------------------------
// Device scratch
// ---------------------------------------------------------------------------
__device__ __half g_xh[(size_t)BATCH * SEQ * DMODEL];      // fp16 x
__device__ __half g_wqkv[(size_t)3 * DMODEL * DMODEL];     // Wq|Wk|Wv concat (N-dim)
__device__ __half g_wo[(size_t)DMODEL * DMODEL];
__device__ __half g_qkvh[3 * QKV_SEG];                     // q|k|v fp16
__device__ __half g_attnh[(size_t)BATCH * SEQ * DMODEL];   // fp16 attn out

// ---------------------------------------------------------------------------
// conversion kernels
// ---------------------------------------------------------------------------
__global__ void f2h_kernel(const float* __restrict__ src, __half* __restrict__ dst, int n4)
{
    int i = blockIdx.x * blockDim.x + threadIdx.x;
    for (; i < n4; i += gridDim.x * blockDim.x) {
        float4 v = *(const float4*)(src + (size_t)i * 4);
        __half2 lo = __floats2half2_rn(v.x, v.y);
        __half2 hi = __floats2half2_rn(v.z, v.w);
        uint2 o;
        o.x = *(uint32_t*)&lo;
        o.y = *(uint32_t*)&hi;
        *(uint2*)(dst + (size_t)i * 4) = o;
    }
}

__global__ void f2h3_kernel(const float* __restrict__ s0, const float* __restrict__ s1,
                            const float* __restrict__ s2, __half* __restrict__ dst)
{
    const int seg4 = (DMODEL * DMODEL) / 4;   // 262144
    int i = blockIdx.x * blockDim.x + threadIdx.x;
    for (; i < 3 * seg4; i += gridDim.x * blockDim.x) {
        int which = i / seg4;
        int loc = i - which * seg4;
        const float* src = (which == 0) ? s0 : (which == 1) ? s1 : s2;
        float4 v = *(const float4*)(src + (size_t)loc * 4);
        __half2 lo = __floats2half2_rn(v.x, v.y);
        __half2 hi = __floats2half2_rn(v.z, v.w);
        uint2 o;
        o.x = *(uint32_t*)&lo;
        o.y = *(uint32_t*)&hi;
        *(uint2*)(dst + (size_t)i * 4) = o;
    }
}

// ---------------------------------------------------------------------------
// cp.async helpers
// ---------------------------------------------------------------------------
__device__ __forceinline__ uint32_t smem_u32(const void* p) {
    uint32_t a;
    asm("{ .reg .u64 t; cvta.to.shared.u64 t, %1; cvt.u32.u64 %0, t; }" : "=r"(a) : "l"(p));
    return a;
}
#define CP_ASYNC16(dst, src) \
    asm volatile("cp.async.cg.shared.global [%0], [%1], 16;" :: "r"(dst), "l"(src))
#define CP_ASYNC16Z(dst, src, sz) \
    asm volatile("cp.async.cg.shared.global [%0], [%1], 16, %2;" :: "r"(dst), "l"(src), "r"(sz))
#define CP_COMMIT() asm volatile("cp.async.commit_group;")
#define CP_WAIT(N)  asm volatile("cp.async.wait_group %0;" :: "n"(N) : "memory")

// ---------------------------------------------------------------------------
// fp16 GEMM v3 (CUTLASS-shape): BM=BN=128, BK=32, 128 threads, 4 warps (2x2),
// warp tile 64x64, 4-stage cp.async, 80KB smem, 2 CTAs/SM.
// LAYOUT 0: C fp32 row-major [M,N] (N=1024), bias = b0
// LAYOUT 1: C half, fused QKV (N=3072), bias segment from b0/b1/b2
// ---------------------------------------------------------------------------
#define BKH   32
#define LDH   40                                  // 32 + 8 pad (halves)
#define NST   4
#define NCH   (DMODEL / BKH)                      // 32
#define TILE_HBYTES (128 * LDH * 2)               // 10240
#define STAGE_BYTES (2 * TILE_HBYTES)             // 20480
#define GEMM_SMEM   (NST * STAGE_BYTES)           // 81920

template <int LAYOUT>
__global__ void __launch_bounds__(128, 2)
gemm_h_kernel(const __half* __restrict__ A, const __half* __restrict__ W,
              const float* __restrict__ b0, const float* __restrict__ b1,
              const float* __restrict__ b2, void* __restrict__ Cv)
{
    extern __shared__ __align__(128) char smem[];
    const uint32_t sbase = smem_u32(smem);
    const int tid  = threadIdx.x;
    const int warp = tid >> 5;
    const int wm   = warp & 1;      // 2 row groups of 64
    const int wn   = warp >> 1;     // 2 col groups of 64
    const int m0   = blockIdx.y * 128;
    const int n0   = blockIdx.x * 128;

    const __half* Abase = A + (size_t)m0 * DMODEL;
    const __half* Bbase = W + (size_t)n0 * DMODEL;

    wmma::fragment<wmma::accumulator, 16, 16, 16, float> acc[4][4];
#pragma unroll
    for (int i = 0; i < 4; i++)
#pragma unroll
        for (int j = 0; j < 4; j++)
            wmma::fill_fragment(acc[i][j], 0.0f);

    auto load_stage = [&](int c, int s) {
        const int k0 = c * BKH;
        uint32_t sa = sbase + s * STAGE_BYTES;
        // A: 128 rows x 4 chunks of 8 halves = 512 cp.async (4/thread)
#pragma unroll
        for (int i = 0; i < 4; i++) {
            int idx = tid + i * 128;
            int r = idx >> 2, ch = (idx & 3) << 3;
            CP_ASYNC16(sa + (r * LDH + ch) * 2,
                       Abase + (size_t)r * DMODEL + k0 + ch);
        }
#pragma unroll
        for (int i = 0; i < 4; i++) {
            int idx = tid + i * 128;
            int r = idx >> 2, ch = (idx & 3) << 3;
            CP_ASYNC16(sa + TILE_HBYTES + (r * LDH + ch) * 2,
                       Bbase + (size_t)r * DMODEL + k0 + ch);
        }
    };

    load_stage(0, 0); CP_COMMIT();
    load_stage(1, 1); CP_COMMIT();
    load_stage(2, 2); CP_COMMIT();

    for (int c = 0; c < NCH; c++) {
        const int s = c & (NST - 1);
        CP_WAIT(2);
        __syncthreads();

        if (c + NST - 1 < NCH) load_stage(c + NST - 1, (c + NST - 1) & (NST - 1));
        CP_COMMIT();

        const __half* As = (const __half*)(smem + s * STAGE_BYTES);
        const __half* Bs = (const __half*)(smem + s * STAGE_BYTES + TILE_HBYTES);
#pragma unroll
        for (int ks = 0; ks < BKH / 16; ks++) {
            wmma::fragment<wmma::matrix_a, 16, 16, 16, __half, wmma::row_major> af[4];
#pragma unroll
            for (int i = 0; i < 4; i++)
                wmma::load_matrix_sync(af[i], As + (wm * 64 + i * 16) * LDH + ks * 16, LDH);
#pragma unroll
            for (int j = 0; j < 4; j++) {
                wmma::fragment<wmma::matrix_b, 16, 16, 16, __half, wmma::col_major> bf;
                wmma::load_matrix_sync(bf, Bs + (wn * 64 + j * 16) * LDH + ks * 16, LDH);
#pragma unroll
                for (int i = 0; i < 4; i++)
                    wmma::mma_sync(acc[i][j], af[i], bf, acc[i][j]);
            }
        }
        // no trailing barrier: next top-of-loop __syncthreads orders stage reuse
    }

    CP_WAIT(0);
    __syncthreads();

    float* stg = (float*)smem;   // 128 x 132 fp32 = 67584 <= 81920
#pragma unroll
    for (int i = 0; i < 4; i++)
#pragma unroll
        for (int j = 0; j < 4; j++)
            wmma::store_matrix_sync(&stg[(wm * 64 + i * 16) * 132 + wn * 64 + j * 16],
                                    acc[i][j], 132, wmma::mem_row_major);
    __syncthreads();

    // bias pointer + segment (uniform per CTA for LAYOUT 1: n0 is 128-aligned)
    const int which = n0 >> 10;
    const float* bp = (LAYOUT == 0) ? b0
                      : (which == 0 ? b0 : (which == 1 ? b1 : b2));
    const int nseg = (LAYOUT == 0) ? n0 : (n0 & 1023);

#pragma unroll
    for (int i = 0; i < 32; i++) {
        int idx = tid + i * 128;        // 4096 quads = 128 x 32
        int r   = idx >> 5;
        int c4  = (idx & 31) << 2;
        float4 v = *(float4*)&stg[r * 132 + c4];
        float4 bv = *(const float4*)&bp[nseg + c4];
        v.x += bv.x; v.y += bv.y; v.z += bv.z; v.w += bv.w;

        if (LAYOUT == 0) {
            float* C = (float*)Cv;
            *(float4*)&C[(size_t)(m0 + r) * DMODEL + n0 + c4] = v;
        } else {
            __half* C = (__half*)Cv;
            int m  = m0 + r;
            int bb = m >> 13;
            int ss = m & (SEQ - 1);
            int nl = nseg + c4;
            int hh = nl >> 6;
            int d0 = nl & 63;
            __half2 lo = __floats2half2_rn(v.x, v.y);
            __half2 hi = __floats2half2_rn(v.z, v.w);
            uint2 o; o.x = *(uint32_t*)&lo; o.y = *(uint32_t*)&hi;
            *(uint2*)&C[(size_t)which * QKV_SEG +
                        (((size_t)bb * NHEADS + hh) * SEQ + ss) * HD + d0] = o;
        }
    }
}

// ---------------------------------------------------------------------------
// Pipelined streaming fp16 attention (validated round-10 version).
// ---------------------------------------------------------------------------
#define WKB 64
#define NJ  6
#define SCLD 68
#define PLD  72
#define KVLD 72
#define KVBUF_BYTES (2 * WKB * KVLD * 2)          // 18432
#define OFF_PH  (128 * SCLD * 4)                  // 34816
#define OFF_KV0 (OFF_PH + 128 * PLD * 2)          // 53248
#define OFF_KV1 (OFF_KV0 + KVBUF_BYTES)           // 71680
#define OFF_RS  (OFF_KV1 + KVBUF_BYTES)           // 90112
#define ATTN_SMEM (OFF_RS + 512)                  // 90624

__global__ void __launch_bounds__(256)
attn_kernel(const __half* __restrict__ Q, const __half* __restrict__ K,
            const __half* __restrict__ V, __half* __restrict__ O)
{
    extern __shared__ __align__(128) char smem[];
    const uint32_t sbase = smem_u32(smem);
    float*  Sc   = (float*)smem;                  // [128][68]
    __half* Ph   = (__half*)(smem + OFF_PH);      // [128][72]
    float*  rsum = (float*)(smem + OFF_RS);       // [128]

    const int tid  = threadIdx.x;
    const int warp = tid >> 5;
    const int n    = blockIdx.x & 63;
    const int h    = (blockIdx.x >> 6) & 15;
    const int b    = blockIdx.x >> 10;
    const size_t base = ((size_t)(b * NHEADS + h)) * SEQ * HD;
    const int kbase = (n - 1) * BS;

    auto load_kv = [&](int j, uint32_t koff) {
        const int kblk = kbase + j * WKB;
#pragma unroll
        for (int i = 0; i < 2; i++) {
            int idx = tid + i * 256;
            int r = idx >> 3, ch = (idx & 7) << 3;
            int kpos = kblk + r;
            bool ok = (kpos >= 0 && kpos < SEQ);
            uint32_t sz = ok ? 16u : 0u;
            size_t off = ok ? (base + (size_t)kpos * HD + ch) : base;
            CP_ASYNC16Z(koff + (r * KVLD + ch) * 2, K + off, sz);
            CP_ASYNC16Z(koff + WKB * KVLD * 2 + (r * KVLD + ch) * 2, V + off, sz);
        }
    };

    {
        const __half* qb = Q + base + (size_t)(n * BS) * HD;
#pragma unroll
        for (int i = 0; i < 4; i++) {
            int idx = tid + i * 256;
            int r = idx >> 3, ch = (idx & 7) << 3;
            *(uint4*)(Ph + r * PLD + ch) = *(const uint4*)(qb + (size_t)r * HD + ch);
        }
    }
    __syncthreads();

    wmma::fragment<wmma::matrix_a, 16, 16, 16, __half, wmma::row_major> qf[4];
#pragma unroll
    for (int ks = 0; ks < 4; ks++)
        wmma::load_matrix_sync(qf[ks], Ph + (warp * 16) * PLD + ks * 16, PLD);
    __syncthreads();

    const int qrow = tid >> 1;
    const int par  = tid & 1;
    int klo = qrow;
    if (kbase < 0 && -kbase > klo) klo = -kbase;
    int khi = qrow + 256;
    {
        int lim = SEQ - kbase - 1;
        if (lim < khi) khi = lim;
    }
    float lsum = 0.f;

    wmma::fragment<wmma::accumulator, 16, 16, 16, float> of[4];
#pragma unroll
    for (int dt = 0; dt < 4; dt++) wmma::fill_fragment(of[dt], 0.0f);

    load_kv(0, sbase + OFF_KV0);
    CP_COMMIT();

    for (int j = 0; j < NJ; j++) {
        const uint32_t koff = sbase + ((j & 1) ? OFF_KV1 : OFF_KV0);

        CP_WAIT(0);
        __syncthreads();

        if (j + 1 < NJ) {
            load_kv(j + 1, sbase + (((j + 1) & 1) ? OFF_KV1 : OFF_KV0));
            CP_COMMIT();
        }

        const __half* Kb = (const __half*)(smem + (koff - sbase));
        const __half* Vb = Kb + WKB * KVLD;

#pragma unroll
        for (int nt = 0; nt < 4; nt++) {
            wmma::fragment<wmma::accumulator, 16, 16, 16, float> sacc;
            wmma::fill_fragment(sacc, 0.0f);
#pragma unroll
            for (int ks = 0; ks < 4; ks++) {
                wmma::fragment<wmma::matrix_b, 16, 16, 16, __half, wmma::col_major> bf;
                wmma::load_matrix_sync(bf, Kb + (nt * 16) * KVLD + ks * 16, KVLD);
                wmma::mma_sync(sacc, qf[ks], bf, sacc);
            }
            wmma::store_matrix_sync(&Sc[(warp * 16) * SCLD + nt * 16], sacc,
                                    SCLD, wmma::mem_row_major);
        }
        __syncwarp();

        {
            float* row = &Sc[qrow * SCLD];
            __half* prow = Ph + qrow * PLD;
            const int c0 = par * 32;
#pragma unroll
            for (int c4 = 0; c4 < 32; c4 += 4) {
                int c = c0 + c4;
                float4 v = *(float4*)&row[c];
                float p0 = 0.f, p1 = 0.f, p2 = 0.f, p3 = 0.f;
                int kk = j * WKB + c;
                if (kk + 0 >= klo && kk + 0 <= khi) p0 = __expf(v.x * 0.125f);
                if (kk + 1 >= klo && kk + 1 <= khi) p1 = __expf(v.y * 0.125f);
                if (kk + 2 >= klo && kk + 2 <= khi) p2 = __expf(v.z * 0.125f);
                if (kk + 3 >= klo && kk + 3 <= khi) p3 = __expf(v.w * 0.125f);
                lsum += p0 + p1 + p2 + p3;
                __half2 lo = __floats2half2_rn(p0, p1);
                __half2 hi = __floats2half2_rn(p2, p3);
                uint2 o; o.x = *(uint32_t*)&lo; o.y = *(uint32_t*)&hi;
                *(uint2*)&prow[c] = o;
            }
        }
        __syncwarp();

#pragma unroll
        for (int ks = 0; ks < 4; ks++) {
            wmma::fragment<wmma::matrix_a, 16, 16, 16, __half, wmma::row_major> pf;
            wmma::load_matrix_sync(pf, Ph + (warp * 16) * PLD + ks * 16, PLD);
#pragma unroll
            for (int dt = 0; dt < 4; dt++) {
                wmma::fragment<wmma::matrix_b, 16, 16, 16, __half, wmma::row_major> vf;
                wmma::load_matrix_sync(vf, Vb + (ks * 16) * KVLD + dt * 16, KVLD);
                wmma::mma_sync(of[dt], pf, vf, of[dt]);
            }
        }
    }

    lsum += __shfl_xor_sync(0xFFFFFFFF, lsum, 1);
    if (par == 0) rsum[qrow] = 1.0f / lsum;

#pragma unroll
    for (int dt = 0; dt < 4; dt++)
        wmma::store_matrix_sync(&Sc[(warp * 16) * SCLD + dt * 16], of[dt],
                                SCLD, wmma::mem_row_major);
    __syncthreads();

#pragma unroll
    for (int i = 0; i < 4; i++) {
        int idx = tid + i * 256;
        int r = idx >> 3, ch = (idx & 7) << 3;
        float s = rsum[r];
        float4 f0 = *(float4*)&Sc[r * SCLD + ch];
        float4 f1 = *(float4*)&Sc[r * SCLD + ch + 4];
        __half2 a = __floats2half2_rn(f0.x * s, f0.y * s);
        __half2 bb2 = __floats2half2_rn(f0.z * s, f0.w * s);
        __half2 cc = __floats2half2_rn(f1.x * s, f1.y * s);
        __half2 d = __floats2half2_rn(f1.z * s, f1.w * s);
        uint4 o;
        o.x = *(uint32_t*)&a; o.y = *(uint32_t*)&bb2;
        o.z = *(uint32_t*)&cc; o.w = *(uint32_t*)&d;
        *(uint4*)&O[((size_t)b * SEQ + (size_t)n * BS + r) * DMODEL + h * HD + ch] = o;
    }
}

// ---------------------------------------------------------------------------
// Launch
// ---------------------------------------------------------------------------
extern "C" void kernel_launch(void* const* d_in, const int* in_sizes, int n_in,
                              void* d_out, int out_size)
{
    const float* x  = (const float*)d_in[0];
    const float* Wq = (const float*)d_in[1];
    const float* bq = (const float*)d_in[2];
    const float* Wk = (const float*)d_in[3];
    const float* bk = (const float*)d_in[4];
    const float* Wv = (const float*)d_in[5];
    const float* bv = (const float*)d_in[6];
    const float* Wo = (const float*)d_in[7];
    const float* bo = (const float*)d_in[8];
    float* out = (float*)d_out;

    __half *xh, *wqkv, *wo, *ah, *qkv;
    cudaGetSymbolAddress((void**)&xh,   g_xh);
    cudaGetSymbolAddress((void**)&wqkv, g_wqkv);
    cudaGetSymbolAddress((void**)&wo,   g_wo);
    cudaGetSymbolAddress((void**)&ah,   g_attnh);
    cudaGetSymbolAddress((void**)&qkv,  g_qkvh);

    cudaFuncSetAttribute(gemm_h_kernel<0>,
                         cudaFuncAttributeMaxDynamicSharedMemorySize, GEMM_SMEM);
    cudaFuncSetAttribute(gemm_h_kernel<1>,
                         cudaFuncAttributeMaxDynamicSharedMemorySize, GEMM_SMEM);
    cudaFuncSetAttribute(attn_kernel,
                         cudaFuncAttributeMaxDynamicSharedMemorySize, ATTN_SMEM);

    const int XN4 = (BATCH * SEQ * DMODEL) / 4;
    const int WN4 = (DMODEL * DMODEL) / 4;
    f2h_kernel<<<1184, 256>>>(x, xh, XN4);
    f2h3_kernel<<<1184, 256>>>(Wq, Wk, Wv, wqkv);
    f2h_kernel<<<592, 256>>>(Wo, wo, WN4);

    // Fused QKV projection: N = 3072
    dim3 qgrid(3 * DMODEL / 128, (BATCH * SEQ) / 128);   // (24,128)
    gemm_h_kernel<1><<<qgrid, 128, GEMM_SMEM>>>(xh, wqkv, bq, bk, bv, qkv);

    attn_kernel<<<BATCH * NHEADS * NBLK, 256, ATTN_SMEM>>>(
        qkv, qkv + QKV_SEG, qkv + 2 * QKV_SEG, ah);

    dim3 ogrid(DMODEL / 128, (BATCH * SEQ) / 128);       // (8,128)
    gemm_h_kernel<0><<<ogrid, 128, GEMM_SMEM>>>(ah, wo, bo, bo, bo, out);
}